// round 1
// baseline (speedup 1.0000x reference)
#include <cuda_runtime.h>
#include <math.h>

#define NN   50000
#define NE   800000
#define FIN  1433
#define FHID 256
#define FOUT 128
#define NCLS 7
#define BN_EPS 1e-5f

// ---------------- scratch (device globals; no runtime allocation) ----------------
__device__ int   g_cnt[NN];
__device__ int   g_offs[NN + 1];
__device__ int   g_cur[NN];
__device__ int   g_csr_src[NE];
__device__ float g_csr_coef[NE];
__device__ float g_dinv[NN];
__device__ float g_invdeg[NN];
__device__ float g_h1[(size_t)NN * FHID];   // x @ W1
__device__ float g_act1[(size_t)NN * FHID]; // ELU(BN(agg1))
__device__ float g_h2[(size_t)NN * FOUT];   // act1 @ W2

// ---------------- graph preprocessing ----------------
__global__ void zero_cnt_kernel() {
    int i = blockIdx.x * blockDim.x + threadIdx.x;
    if (i < NN) g_cnt[i] = 0;
}

__global__ void count_deg_kernel(const int* __restrict__ dst) {
    int e = blockIdx.x * blockDim.x + threadIdx.x;
    if (e < NE) atomicAdd(&g_cnt[dst[e]], 1);
}

__global__ void node_prep_kernel() {
    int n = blockIdx.x * blockDim.x + threadIdx.x;
    if (n < NN) {
        float d = (float)g_cnt[n] + 1.0f;   // +1 self loop
        g_dinv[n]   = rsqrtf(d);
        g_invdeg[n] = 1.0f / d;
    }
}

// single-block exclusive scan over g_cnt -> g_offs  (blockDim must be 1024)
__global__ void scan_offsets_kernel() {
    __shared__ int wsum[32];
    int t = threadIdx.x;
    int lane = t & 31;
    int w = t >> 5;
    int carry = 0;
    for (int base = 0; base < NN; base += 1024) {
        int i = base + t;
        int v = (i < NN) ? g_cnt[i] : 0;
        int x = v;
        #pragma unroll
        for (int o = 1; o < 32; o <<= 1) {
            int y = __shfl_up_sync(0xffffffffu, x, o);
            if (lane >= o) x += y;
        }
        if (lane == 31) wsum[w] = x;
        __syncthreads();
        if (w == 0) {
            int s = wsum[lane];
            #pragma unroll
            for (int o = 1; o < 32; o <<= 1) {
                int y = __shfl_up_sync(0xffffffffu, s, o);
                if (lane >= o) s += y;
            }
            wsum[lane] = s;
        }
        __syncthreads();
        int prefix = (w > 0) ? wsum[w - 1] : 0;
        int incl = x + prefix;
        if (i < NN) g_offs[i] = carry + incl - v;
        int total = wsum[31];
        carry += total;
        __syncthreads();
    }
    if (t == 0) g_offs[NN] = carry;
}

__global__ void copy_cur_kernel() {
    int i = blockIdx.x * blockDim.x + threadIdx.x;
    if (i < NN) g_cur[i] = g_offs[i];
}

__global__ void fill_csr_kernel(const int* __restrict__ src, const int* __restrict__ dst) {
    int e = blockIdx.x * blockDim.x + threadIdx.x;
    if (e < NE) {
        int s = src[e];
        int d = dst[e];
        int p = atomicAdd(&g_cur[d], 1);
        g_csr_src[p]  = s;
        g_csr_coef[p] = g_dinv[s] * g_dinv[d];
    }
}

// ---------------- SGEMM: C[M,NMAT] = A[M,KMAT] @ B[KMAT,NMAT] ----------------
// classic 128x128x8 tiling, 256 threads, 8x8 per thread
template <int NMAT, int KMAT, int LAYER>
__global__ __launch_bounds__(256)
void sgemm128_kernel(const float* __restrict__ Aext, const float* __restrict__ B) {
    const float* A = (LAYER == 1) ? Aext : (const float*)g_act1;
    float*       C = (LAYER == 1) ? (float*)g_h1 : (float*)g_h2;
    const int M = NN;

    __shared__ float As[8][128];
    __shared__ float Bs[8][128];

    int tid = threadIdx.x;
    int tx = tid & 15;       // 0..15
    int ty = tid >> 4;       // 0..15
    int m0 = blockIdx.y * 128;
    int n0 = blockIdx.x * 128;

    int a_row = tid >> 1;           // 0..127
    int a_col = (tid & 1) * 4;      // 0 or 4
    int b_row = tid >> 5;           // 0..7
    int b_col = (tid & 31) * 4;     // 0..124

    bool a_valid_row = (m0 + a_row) < M;
    const float* Ag = A + (size_t)(m0 + a_row) * KMAT;

    float acc[8][8];
    #pragma unroll
    for (int i = 0; i < 8; i++)
        #pragma unroll
        for (int j = 0; j < 8; j++) acc[i][j] = 0.0f;

    for (int k0 = 0; k0 < KMAT; k0 += 8) {
        // load A tile (scalar, K stride may be odd)
        #pragma unroll
        for (int i = 0; i < 4; i++) {
            int kc = k0 + a_col + i;
            float v = (a_valid_row && kc < KMAT) ? Ag[kc] : 0.0f;
            As[a_col + i][a_row] = v;
        }
        // load B tile (vectorized: NMAT % 4 == 0)
        {
            int kr = k0 + b_row;
            float4 v = make_float4(0.f, 0.f, 0.f, 0.f);
            if (kr < KMAT) v = *(const float4*)(B + (size_t)kr * NMAT + n0 + b_col);
            *(float4*)(&Bs[b_row][b_col]) = v;
        }
        __syncthreads();

        #pragma unroll
        for (int kk = 0; kk < 8; kk++) {
            float ra[8], rb[8];
            const float4* ap = (const float4*)(&As[kk][ty * 8]);
            const float4* bp = (const float4*)(&Bs[kk][tx * 8]);
            float4 a0 = ap[0], a1 = ap[1];
            float4 b0 = bp[0], b1 = bp[1];
            ra[0] = a0.x; ra[1] = a0.y; ra[2] = a0.z; ra[3] = a0.w;
            ra[4] = a1.x; ra[5] = a1.y; ra[6] = a1.z; ra[7] = a1.w;
            rb[0] = b0.x; rb[1] = b0.y; rb[2] = b0.z; rb[3] = b0.w;
            rb[4] = b1.x; rb[5] = b1.y; rb[6] = b1.z; rb[7] = b1.w;
            #pragma unroll
            for (int i = 0; i < 8; i++)
                #pragma unroll
                for (int j = 0; j < 8; j++)
                    acc[i][j] += ra[i] * rb[j];
        }
        __syncthreads();
    }

    #pragma unroll
    for (int i = 0; i < 8; i++) {
        int r = m0 + ty * 8 + i;
        if (r < M) {
            float4* cp = (float4*)(C + (size_t)r * NMAT + n0 + tx * 8);
            cp[0] = make_float4(acc[i][0], acc[i][1], acc[i][2], acc[i][3]);
            cp[1] = make_float4(acc[i][4], acc[i][5], acc[i][6], acc[i][7]);
        }
    }
}

// ---------------- fused aggregate + bias + BN + ELU (gather, no atomics) ----------------
__device__ __forceinline__ float elu1(float x) { return x > 0.0f ? x : expm1f(x); }

template <int F, int LAYER>
__global__ __launch_bounds__(256)
void aggregate_fused_kernel(const float* __restrict__ bias,
                            const float* __restrict__ bnw, const float* __restrict__ bnb,
                            const float* __restrict__ bnm, const float* __restrict__ bnv,
                            float* __restrict__ outp) {
    const float* h = (LAYER == 1) ? (const float*)g_h1 : (const float*)g_h2;
    float* out = (LAYER == 1) ? (float*)g_act1 : outp;

    constexpr int V = F / 128;   // float4 chunks per lane
    int warp = (blockIdx.x * blockDim.x + threadIdx.x) >> 5;
    int lane = threadIdx.x & 31;
    if (warp >= NN) return;
    int node = warp;

    float4 acc[V];
    // self-loop term: h[node] * (1/deg)
    {
        const float4* hn = (const float4*)(h + (size_t)node * F);
        float idg = g_invdeg[node];
        #pragma unroll
        for (int t = 0; t < V; t++) {
            float4 v = hn[lane + 32 * t];
            acc[t] = make_float4(v.x * idg, v.y * idg, v.z * idg, v.w * idg);
        }
    }

    int beg = g_offs[node];
    int end = g_offs[node + 1];
    for (int j = beg; j < end; j++) {
        int   s = g_csr_src[j];
        float c = g_csr_coef[j];
        const float4* hs = (const float4*)(h + (size_t)s * F);
        #pragma unroll
        for (int t = 0; t < V; t++) {
            float4 v = hs[lane + 32 * t];
            acc[t].x += v.x * c;
            acc[t].y += v.y * c;
            acc[t].z += v.z * c;
            acc[t].w += v.w * c;
        }
    }

    #pragma unroll
    for (int t = 0; t < V; t++) {
        int f = (lane + 32 * t) * 4;
        float4 bb = *(const float4*)(bias + f);
        float4 w  = *(const float4*)(bnw + f);
        float4 b2 = *(const float4*)(bnb + f);
        float4 mn = *(const float4*)(bnm + f);
        float4 vr = *(const float4*)(bnv + f);
        float4 o;
        o.x = elu1((acc[t].x + bb.x - mn.x) * rsqrtf(vr.x + BN_EPS) * w.x + b2.x);
        o.y = elu1((acc[t].y + bb.y - mn.y) * rsqrtf(vr.y + BN_EPS) * w.y + b2.y);
        o.z = elu1((acc[t].z + bb.z - mn.z) * rsqrtf(vr.z + BN_EPS) * w.z + b2.z);
        o.w = elu1((acc[t].w + bb.w - mn.w) * rsqrtf(vr.w + BN_EPS) * w.w + b2.w);
        ((float4*)(out + (size_t)node * F))[lane + 32 * t] = o;
    }
}

// ---------------- head: z = softmax(h @ Wp + bp) ----------------
__global__ __launch_bounds__(256)
void head_kernel(const float* __restrict__ h, const float* __restrict__ Wp,
                 const float* __restrict__ bp, float* __restrict__ z) {
    __shared__ float sW[FOUT * NCLS + NCLS];
    for (int i = threadIdx.x; i < FOUT * NCLS; i += blockDim.x) sW[i] = Wp[i];
    for (int i = threadIdx.x; i < NCLS; i += blockDim.x) sW[FOUT * NCLS + i] = bp[i];
    __syncthreads();

    int node = blockIdx.x * blockDim.x + threadIdx.x;
    if (node >= NN) return;

    float acc[NCLS];
    #pragma unroll
    for (int k = 0; k < NCLS; k++) acc[k] = sW[FOUT * NCLS + k];

    const float4* hp = (const float4*)(h + (size_t)node * FOUT);
    #pragma unroll 8
    for (int f4 = 0; f4 < FOUT / 4; f4++) {
        float4 v = hp[f4];
        float hv[4] = {v.x, v.y, v.z, v.w};
        #pragma unroll
        for (int j = 0; j < 4; j++) {
            int f = f4 * 4 + j;
            #pragma unroll
            for (int k = 0; k < NCLS; k++) acc[k] += hv[j] * sW[f * NCLS + k];
        }
    }

    float m = acc[0];
    #pragma unroll
    for (int k = 1; k < NCLS; k++) m = fmaxf(m, acc[k]);
    float ssum = 0.0f;
    #pragma unroll
    for (int k = 0; k < NCLS; k++) { acc[k] = expf(acc[k] - m); ssum += acc[k]; }
    float inv = 1.0f / ssum;
    float* zp = z + (size_t)node * NCLS;
    #pragma unroll
    for (int k = 0; k < NCLS; k++) zp[k] = acc[k] * inv;
}

// ---------------- launch ----------------
extern "C" void kernel_launch(void* const* d_in, const int* in_sizes, int n_in,
                              void* d_out, int out_size) {
    const float* x    = (const float*)d_in[0];
    const int*   ei   = (const int*)d_in[1];
    const float* W1   = (const float*)d_in[2];
    const float* b1   = (const float*)d_in[3];
    const float* bn1w = (const float*)d_in[4];
    const float* bn1b = (const float*)d_in[5];
    const float* bn1m = (const float*)d_in[6];
    const float* bn1v = (const float*)d_in[7];
    const float* W2   = (const float*)d_in[8];
    const float* b2   = (const float*)d_in[9];
    const float* bn2w = (const float*)d_in[10];
    const float* bn2b = (const float*)d_in[11];
    const float* bn2m = (const float*)d_in[12];
    const float* bn2v = (const float*)d_in[13];
    const float* Wp   = (const float*)d_in[14];
    const float* bp   = (const float*)d_in[15];

    const int* src = ei;           // edge_index[0]
    const int* dst = ei + NE;      // edge_index[1]

    float* out_h = (float*)d_out;                       // [NN, FOUT]
    float* out_z = out_h + (size_t)NN * FOUT;           // [NN, NCLS]

    const int NODE_BLKS = (NN + 255) / 256;   // 196
    const int EDGE_BLKS = (NE + 255) / 256;   // 3125

    // CSR build
    zero_cnt_kernel<<<NODE_BLKS, 256>>>();
    count_deg_kernel<<<EDGE_BLKS, 256>>>(dst);
    node_prep_kernel<<<NODE_BLKS, 256>>>();
    scan_offsets_kernel<<<1, 1024>>>();
    copy_cur_kernel<<<NODE_BLKS, 256>>>();
    fill_csr_kernel<<<EDGE_BLKS, 256>>>(src, dst);

    // layer 1
    sgemm128_kernel<FHID, FIN, 1><<<dim3(FHID / 128, (NN + 127) / 128), 256>>>(x, W1);
    aggregate_fused_kernel<FHID, 1><<<(NN * 32) / 256, 256>>>(b1, bn1w, bn1b, bn1m, bn1v, nullptr);

    // layer 2
    sgemm128_kernel<FOUT, FHID, 2><<<dim3(FOUT / 128, (NN + 127) / 128), 256>>>(nullptr, W2);
    aggregate_fused_kernel<FOUT, 2><<<(NN * 32) / 256, 256>>>(b2, bn2w, bn2b, bn2m, bn2v, out_h);

    // head
    head_kernel<<<NODE_BLKS, 256>>>(out_h, Wp, bp, out_z);
}

// round 3
// speedup vs baseline: 1.9858x; 1.9858x over previous
#include <cuda_runtime.h>
#include <math.h>
#include <stdint.h>

#define NN   50000
#define NE   800000
#define FIN  1433
#define KPAD1 1440
#define FHID 256
#define FOUT 128
#define NCLS 7
#define BN_EPS 1e-5f

// ---------------- scratch (device globals; no runtime allocation) ----------------
__device__ int   g_cnt[NN];
__device__ int   g_offs[NN + 1];
__device__ int   g_cur[NN];
__device__ int   g_bsum[64];
__device__ int   g_csr_src[NE];
__device__ float g_csr_coef[NE];
__device__ float g_dinv[NN];
__device__ float g_invdeg[NN];
__device__ float g_xpad[(size_t)NN * KPAD1];    // x zero-padded to K=1440, tf32-rounded
__device__ float g_w1r[(size_t)KPAD1 * FHID];   // W1 [K,N] tf32-rounded, K padded w/ zeros
__device__ float g_w2r[(size_t)FHID * FOUT];    // W2 [K,N] tf32-rounded
__device__ float g_h1[(size_t)NN * FHID];       // x @ W1
__device__ float g_act1[(size_t)NN * FHID];     // ELU(BN(agg1)), tf32-rounded
__device__ float g_h2[(size_t)NN * FOUT];       // act1 @ W2

// ================= helpers =================
__device__ __forceinline__ uint32_t smem_u32(const void* p) {
    uint32_t a;
    asm("{ .reg .u64 t; cvta.to.shared.u64 t, %1; cvt.u32.u64 %0, t; }" : "=r"(a) : "l"(p));
    return a;
}

__device__ __forceinline__ float tf32r(float x) {
    uint32_t u;
    asm("cvt.rna.tf32.f32 %0, %1;" : "=r"(u) : "f"(x));
    return __uint_as_float(u);
}

__device__ __forceinline__ void cp16(uint32_t dst, const void* src, int srcsize) {
    asm volatile("cp.async.cg.shared.global [%0], [%1], 16, %2;"
                 :: "r"(dst), "l"(src), "r"(srcsize) : "memory");
}

__device__ __forceinline__ void mma_tf32(float* c, const uint32_t* a, const uint32_t* b) {
    asm volatile(
        "mma.sync.aligned.m16n8k8.row.col.f32.tf32.tf32.f32 "
        "{%0,%1,%2,%3}, {%4,%5,%6,%7}, {%8,%9}, {%0,%1,%2,%3};"
        : "+f"(c[0]), "+f"(c[1]), "+f"(c[2]), "+f"(c[3])
        : "r"(a[0]), "r"(a[1]), "r"(a[2]), "r"(a[3]), "r"(b[0]), "r"(b[1]));
}

// ================= preprocessing =================
__global__ void pad_x_kernel(const float* __restrict__ x) {
    long idx = (long)blockIdx.x * blockDim.x + threadIdx.x;
    if (idx >= (long)NN * KPAD1) return;
    int row = (int)(idx / KPAD1);
    int col = (int)(idx - (long)row * KPAD1);
    g_xpad[idx] = (col < FIN) ? tf32r(x[(long)row * FIN + col]) : 0.0f;
}

__global__ void round_w1_kernel(const float* __restrict__ W1) {
    int idx = blockIdx.x * blockDim.x + threadIdx.x;
    if (idx >= KPAD1 * FHID) return;
    int k = idx / FHID;
    g_w1r[idx] = (k < FIN) ? tf32r(W1[idx]) : 0.0f;
}

__global__ void round_w2_kernel(const float* __restrict__ W2) {
    int idx = blockIdx.x * blockDim.x + threadIdx.x;
    if (idx >= FHID * FOUT) return;
    g_w2r[idx] = tf32r(W2[idx]);
}

// ================= CSR build =================
__global__ void zero_cnt_kernel() {
    int i = blockIdx.x * blockDim.x + threadIdx.x;
    if (i < NN) g_cnt[i] = 0;
}

__global__ void count_deg_kernel(const int* __restrict__ dst) {
    int e = blockIdx.x * blockDim.x + threadIdx.x;
    if (e < NE) atomicAdd(&g_cnt[dst[e]], 1);
}

__global__ __launch_bounds__(1024)
void scan_block_kernel() {
    __shared__ int ws[32];
    int t = threadIdx.x, b = blockIdx.x;
    int i = b * 1024 + t;
    int v = (i < NN) ? g_cnt[i] : 0;
    if (i < NN) {
        float d = (float)v + 1.0f;
        g_dinv[i]   = rsqrtf(d);
        g_invdeg[i] = 1.0f / d;
    }
    int lane = t & 31, w = t >> 5;
    int x = v;
    #pragma unroll
    for (int o = 1; o < 32; o <<= 1) {
        int y = __shfl_up_sync(0xffffffffu, x, o);
        if (lane >= o) x += y;
    }
    if (lane == 31) ws[w] = x;
    __syncthreads();
    if (w == 0) {
        int s = ws[lane];
        #pragma unroll
        for (int o = 1; o < 32; o <<= 1) {
            int y = __shfl_up_sync(0xffffffffu, s, o);
            if (lane >= o) s += y;
        }
        ws[lane] = s;
    }
    __syncthreads();
    int pre = (w > 0) ? ws[w - 1] : 0;
    if (i < NN) g_offs[i] = pre + x - v;
    if (t == 1023) g_bsum[b] = pre + x;
}

__global__ void scan_bsum_kernel(int nblk) {
    __shared__ int s[64];
    int t = threadIdx.x;
    s[t] = (t < nblk) ? g_bsum[t] : 0;
    __syncthreads();
    if (t == 0) {
        int acc = 0;
        for (int i = 0; i < nblk; i++) { int v = s[i]; s[i] = acc; acc += v; }
    }
    __syncthreads();
    if (t < nblk) g_bsum[t] = s[t];
}

__global__ __launch_bounds__(1024)
void scan_add_kernel() {
    int t = threadIdx.x, b = blockIdx.x;
    int i = b * 1024 + t;
    if (i < NN) {
        int o = g_offs[i] + g_bsum[b];
        g_offs[i] = o;
        g_cur[i]  = o;
    }
    if (i == 0) g_offs[NN] = NE;
}

__global__ void fill_csr_kernel(const int* __restrict__ src, const int* __restrict__ dst) {
    int e = blockIdx.x * blockDim.x + threadIdx.x;
    if (e < NE) {
        int s = src[e];
        int d = dst[e];
        int p = atomicAdd(&g_cur[d], 1);
        g_csr_src[p]  = s;
        g_csr_coef[p] = g_dinv[s] * g_dinv[d];
    }
}

// ================= tf32 mma.sync GEMM =================
// C[M, NMAT] = A[M, KA] @ B[KA(+pad), NMAT].  Block 128x128x16, 8 warps (4x2),
// warp tile 32x64, m16n8k8 tf32 mma, 3-stage cp.async pipeline.
template <int NMAT, int KA, int KTILES>
__global__ __launch_bounds__(256)
void mma_gemm_kernel(const float* __restrict__ A, const float* __restrict__ B,
                     float* __restrict__ C) {
    constexpr int S = 3;
    constexpr int AS_STRIDE = 20;                 // floats per A smem row (bank-safe, 16B-mult)
    constexpr int BS_STRIDE = 136;                // floats per B smem row (bank-safe, 16B-mult)
    constexpr int A_FLOATS = 128 * AS_STRIDE;     // 2560
    constexpr int B_FLOATS = 16 * BS_STRIDE;      // 2176
    constexpr int STG = A_FLOATS + B_FLOATS;      // 4736 floats/stage

    extern __shared__ float sm[];
    uint32_t smb = smem_u32(sm);

    int tid  = threadIdx.x;
    int lane = tid & 31;
    int w    = tid >> 5;
    int g    = lane >> 2;     // 0..7
    int tig  = lane & 3;      // 0..3
    int wm   = (w & 3) * 32;  // warp M offset in block
    int wn   = (w >> 2) * 64; // warp N offset in block
    int m0   = blockIdx.y * 128;
    int n0   = blockIdx.x * 128;

    // cp.async assignments
    int a_row = tid >> 1;              // 0..127
    int a_col = (tid & 1) * 8;         // 0 or 8
    int a_m   = m0 + a_row;
    const float* Ag = A + (size_t)(a_m < NN ? a_m : 0) * KA + a_col;
    int a_src = (a_m < NN) ? 16 : 0;
    uint32_t a_dst0 = smb + (uint32_t)(a_row * AS_STRIDE + a_col) * 4;

    int b_row = tid >> 4;              // 0..15
    int b_col = (tid & 15) * 8;        // 0..120
    const float* Bg = B + (size_t)b_row * NMAT + n0 + b_col;
    uint32_t b_dst0 = smb + (uint32_t)(A_FLOATS + b_row * BS_STRIDE + b_col) * 4;

    float c[2][8][4];
    #pragma unroll
    for (int mt = 0; mt < 2; mt++)
        #pragma unroll
        for (int nt = 0; nt < 8; nt++)
            #pragma unroll
            for (int q = 0; q < 4; q++) c[mt][nt][q] = 0.0f;

    // prologue: stages 0..S-2
    #pragma unroll
    for (int s = 0; s < S - 1; s++) {
        uint32_t off = (uint32_t)(s * STG) * 4;
        const float* ga = Ag + s * 16;
        cp16(a_dst0 + off,      ga,     a_src);
        cp16(a_dst0 + off + 16, ga + 4, a_src);
        const float* gb = Bg + (size_t)(s * 16) * NMAT;
        cp16(b_dst0 + off,      gb,     16);
        cp16(b_dst0 + off + 16, gb + 4, 16);
        asm volatile("cp.async.commit_group;" ::: "memory");
    }

    for (int kt = 0; kt < KTILES; kt++) {
        asm volatile("cp.async.wait_group %0;" :: "n"(S - 2) : "memory");
        __syncthreads();

        // prefetch stage kt+S-1 into slot (kt+S-1)%S (freed by barrier above)
        {
            int nk = kt + S - 1;
            if (nk < KTILES) {
                uint32_t off = (uint32_t)((nk % S) * STG) * 4;
                const float* ga = Ag + nk * 16;
                cp16(a_dst0 + off,      ga,     a_src);
                cp16(a_dst0 + off + 16, ga + 4, a_src);
                const float* gb = Bg + (size_t)(nk * 16) * NMAT;
                cp16(b_dst0 + off,      gb,     16);
                cp16(b_dst0 + off + 16, gb + 4, 16);
            }
            asm volatile("cp.async.commit_group;" ::: "memory");
        }

        const float* As = sm + (kt % S) * STG;
        const float* Bs = As + A_FLOATS;

        #pragma unroll
        for (int kk = 0; kk < 16; kk += 8) {
            uint32_t a[2][4], b[8][2];
            #pragma unroll
            for (int mt = 0; mt < 2; mt++) {
                int r = wm + mt * 16 + g;
                a[mt][0] = __float_as_uint(As[r * AS_STRIDE + kk + tig]);
                a[mt][1] = __float_as_uint(As[(r + 8) * AS_STRIDE + kk + tig]);
                a[mt][2] = __float_as_uint(As[r * AS_STRIDE + kk + tig + 4]);
                a[mt][3] = __float_as_uint(As[(r + 8) * AS_STRIDE + kk + tig + 4]);
            }
            #pragma unroll
            for (int nt = 0; nt < 8; nt++) {
                int ccol = wn + nt * 8 + g;
                b[nt][0] = __float_as_uint(Bs[(kk + tig) * BS_STRIDE + ccol]);
                b[nt][1] = __float_as_uint(Bs[(kk + tig + 4) * BS_STRIDE + ccol]);
            }
            #pragma unroll
            for (int mt = 0; mt < 2; mt++)
                #pragma unroll
                for (int nt = 0; nt < 8; nt++)
                    mma_tf32(c[mt][nt], a[mt], b[nt]);
        }
    }

    // epilogue
    #pragma unroll
    for (int mt = 0; mt < 2; mt++) {
        int r0 = m0 + wm + mt * 16 + g;
        #pragma unroll
        for (int nt = 0; nt < 8; nt++) {
            int col = n0 + wn + nt * 8 + 2 * tig;
            if (r0 < NN)
                *(float2*)(C + (size_t)r0 * NMAT + col) = make_float2(c[mt][nt][0], c[mt][nt][1]);
            if (r0 + 8 < NN)
                *(float2*)(C + (size_t)(r0 + 8) * NMAT + col) = make_float2(c[mt][nt][2], c[mt][nt][3]);
        }
    }
}

// ================= fused aggregate + bias + BN + ELU =================
__device__ __forceinline__ float elu1(float x) { return x > 0.0f ? x : expm1f(x); }

template <int F, int LAYER>
__global__ __launch_bounds__(256)
void aggregate_fused_kernel(const float* __restrict__ bias,
                            const float* __restrict__ bnw, const float* __restrict__ bnb,
                            const float* __restrict__ bnm, const float* __restrict__ bnv,
                            float* __restrict__ outp) {
    const float* h = (LAYER == 1) ? (const float*)g_h1 : (const float*)g_h2;
    float* out = (LAYER == 1) ? (float*)g_act1 : outp;

    constexpr int V = F / 128;
    int warp = (blockIdx.x * blockDim.x + threadIdx.x) >> 5;
    int lane = threadIdx.x & 31;
    if (warp >= NN) return;
    int node = warp;

    float4 acc[V];
    {
        const float4* hn = (const float4*)(h + (size_t)node * F);
        float idg = g_invdeg[node];
        #pragma unroll
        for (int t = 0; t < V; t++) {
            float4 v = hn[lane + 32 * t];
            acc[t] = make_float4(v.x * idg, v.y * idg, v.z * idg, v.w * idg);
        }
    }

    int beg = g_offs[node];
    int end = g_offs[node + 1];
    for (int j = beg; j < end; j++) {
        int   s = g_csr_src[j];
        float cc = g_csr_coef[j];
        const float4* hs = (const float4*)(h + (size_t)s * F);
        #pragma unroll
        for (int t = 0; t < V; t++) {
            float4 v = hs[lane + 32 * t];
            acc[t].x += v.x * cc;
            acc[t].y += v.y * cc;
            acc[t].z += v.z * cc;
            acc[t].w += v.w * cc;
        }
    }

    #pragma unroll
    for (int t = 0; t < V; t++) {
        int f = (lane + 32 * t) * 4;
        float4 bb = *(const float4*)(bias + f);
        float4 w  = *(const float4*)(bnw + f);
        float4 b2 = *(const float4*)(bnb + f);
        float4 mn = *(const float4*)(bnm + f);
        float4 vr = *(const float4*)(bnv + f);
        float4 o;
        o.x = elu1((acc[t].x + bb.x - mn.x) * rsqrtf(vr.x + BN_EPS) * w.x + b2.x);
        o.y = elu1((acc[t].y + bb.y - mn.y) * rsqrtf(vr.y + BN_EPS) * w.y + b2.y);
        o.z = elu1((acc[t].z + bb.z - mn.z) * rsqrtf(vr.z + BN_EPS) * w.z + b2.z);
        o.w = elu1((acc[t].w + bb.w - mn.w) * rsqrtf(vr.w + BN_EPS) * w.w + b2.w);
        if (LAYER == 1) {   // act1 feeds tf32 GEMM2: pre-round for mma accuracy
            o.x = tf32r(o.x); o.y = tf32r(o.y); o.z = tf32r(o.z); o.w = tf32r(o.w);
        }
        ((float4*)(out + (size_t)node * F))[lane + 32 * t] = o;
    }
}

// ================= head: z = softmax(h @ Wp + bp) =================
__global__ __launch_bounds__(256)
void head_kernel(const float* __restrict__ h, const float* __restrict__ Wp,
                 const float* __restrict__ bp, float* __restrict__ z) {
    __shared__ float sW[FOUT * NCLS + NCLS];
    for (int i = threadIdx.x; i < FOUT * NCLS; i += blockDim.x) sW[i] = Wp[i];
    for (int i = threadIdx.x; i < NCLS; i += blockDim.x) sW[FOUT * NCLS + i] = bp[i];
    __syncthreads();

    int node = blockIdx.x * blockDim.x + threadIdx.x;
    if (node >= NN) return;

    float acc[NCLS];
    #pragma unroll
    for (int k = 0; k < NCLS; k++) acc[k] = sW[FOUT * NCLS + k];

    const float4* hp = (const float4*)(h + (size_t)node * FOUT);
    #pragma unroll 8
    for (int f4 = 0; f4 < FOUT / 4; f4++) {
        float4 v = hp[f4];
        float hv[4] = {v.x, v.y, v.z, v.w};
        #pragma unroll
        for (int j = 0; j < 4; j++) {
            int f = f4 * 4 + j;
            #pragma unroll
            for (int k = 0; k < NCLS; k++) acc[k] += hv[j] * sW[f * NCLS + k];
        }
    }

    float m = acc[0];
    #pragma unroll
    for (int k = 1; k < NCLS; k++) m = fmaxf(m, acc[k]);
    float ssum = 0.0f;
    #pragma unroll
    for (int k = 0; k < NCLS; k++) { acc[k] = expf(acc[k] - m); ssum += acc[k]; }
    float inv = 1.0f / ssum;
    float* zp = z + (size_t)node * NCLS;
    #pragma unroll
    for (int k = 0; k < NCLS; k++) zp[k] = acc[k] * inv;
}

// ================= host =================
extern "C" void kernel_launch(void* const* d_in, const int* in_sizes, int n_in,
                              void* d_out, int out_size) {
    const float* x    = (const float*)d_in[0];
    const int*   ei   = (const int*)d_in[1];
    const float* W1   = (const float*)d_in[2];
    const float* b1   = (const float*)d_in[3];
    const float* bn1w = (const float*)d_in[4];
    const float* bn1b = (const float*)d_in[5];
    const float* bn1m = (const float*)d_in[6];
    const float* bn1v = (const float*)d_in[7];
    const float* W2   = (const float*)d_in[8];
    const float* b2   = (const float*)d_in[9];
    const float* bn2w = (const float*)d_in[10];
    const float* bn2b = (const float*)d_in[11];
    const float* bn2m = (const float*)d_in[12];
    const float* bn2v = (const float*)d_in[13];
    const float* Wp   = (const float*)d_in[14];
    const float* bp   = (const float*)d_in[15];

    const int* src = ei;
    const int* dst = ei + NE;

    float* out_h = (float*)d_out;
    float* out_z = out_h + (size_t)NN * FOUT;

    void *p_xpad, *p_w1r, *p_w2r, *p_act1, *p_h1, *p_h2;
    cudaGetSymbolAddress(&p_xpad, g_xpad);
    cudaGetSymbolAddress(&p_w1r,  g_w1r);
    cudaGetSymbolAddress(&p_w2r,  g_w2r);
    cudaGetSymbolAddress(&p_act1, g_act1);
    cudaGetSymbolAddress(&p_h1,   g_h1);
    cudaGetSymbolAddress(&p_h2,   g_h2);

    constexpr int STG_BYTES = (128 * 20 + 16 * 136) * 4;  // 18944
    constexpr int SMEM_GEMM = 3 * STG_BYTES;              // 56832
    static bool attr_set = false;
    if (!attr_set) {
        cudaFuncSetAttribute(mma_gemm_kernel<FHID, KPAD1, KPAD1 / 16>,
                             cudaFuncAttributeMaxDynamicSharedMemorySize, SMEM_GEMM);
        cudaFuncSetAttribute(mma_gemm_kernel<FOUT, FHID, FHID / 16>,
                             cudaFuncAttributeMaxDynamicSharedMemorySize, SMEM_GEMM);
        attr_set = true;
    }

    const int NODE_BLKS = (NN + 255) / 256;
    const int EDGE_BLKS = (NE + 255) / 256;
    const int SCAN_BLKS = (NN + 1023) / 1024;   // 49
    const int MTILES    = (NN + 127) / 128;     // 391

    // preprocessing (pad + tf32 rounding)
    {
        long tot = (long)NN * KPAD1;
        pad_x_kernel<<<(unsigned)((tot + 255) / 256), 256>>>(x);
        round_w1_kernel<<<(KPAD1 * FHID + 255) / 256, 256>>>(W1);
        round_w2_kernel<<<(FHID * FOUT + 255) / 256, 256>>>(W2);
    }

    // CSR build
    zero_cnt_kernel<<<NODE_BLKS, 256>>>();
    count_deg_kernel<<<EDGE_BLKS, 256>>>(dst);
    scan_block_kernel<<<SCAN_BLKS, 1024>>>();
    scan_bsum_kernel<<<1, 64>>>(SCAN_BLKS);
    scan_add_kernel<<<SCAN_BLKS, 1024>>>();
    fill_csr_kernel<<<EDGE_BLKS, 256>>>(src, dst);

    // layer 1
    mma_gemm_kernel<FHID, KPAD1, KPAD1 / 16>
        <<<dim3(2, MTILES), 256, SMEM_GEMM>>>((const float*)p_xpad, (const float*)p_w1r, (float*)p_h1);
    aggregate_fused_kernel<FHID, 1><<<(NN * 32) / 256, 256>>>(b1, bn1w, bn1b, bn1m, bn1v, nullptr);

    // layer 2
    mma_gemm_kernel<FOUT, FHID, FHID / 16>
        <<<dim3(1, MTILES), 256, SMEM_GEMM>>>((const float*)p_act1, (const float*)p_w2r, (float*)p_h2);
    aggregate_fused_kernel<FOUT, 2><<<(NN * 32) / 256, 256>>>(b2, bn2w, bn2b, bn2m, bn2v, out_h);

    // head
    head_kernel<<<NODE_BLKS, 256>>>(out_h, Wp, bp, out_z);
}

// round 4
// speedup vs baseline: 2.2556x; 1.1358x over previous
#include <cuda_runtime.h>
#include <math.h>
#include <stdint.h>

#define NN   50000
#define NE   800000
#define FIN  1433
#define KPAD1 1440
#define FHID 256
#define FOUT 128
#define NCLS 7
#define BN_EPS 1e-5f

// ---------------- scratch (device globals; no runtime allocation) ----------------
__device__ int   g_cnt[NN];
__device__ int   g_offs[NN + 1];
__device__ int   g_cur[NN];
__device__ int   g_bsum[64];
__device__ int   g_csr_src[NE];
__device__ float g_csr_coef[NE];
__device__ float g_dinv[NN];
__device__ float g_invdeg[NN];
__device__ float g_w1r[(size_t)KPAD1 * FHID];   // W1 [K,N] tf32-rounded, K zero-padded
__device__ float g_w2r[(size_t)FHID * FOUT];    // W2 [K,N] tf32-rounded
__device__ float g_h1[(size_t)NN * FHID];       // x @ W1
__device__ float g_act1[(size_t)NN * FHID];     // ELU(BN(agg1)), tf32-rounded
__device__ float g_h2[(size_t)NN * FOUT];       // act1 @ W2

// ================= helpers =================
__device__ __forceinline__ uint32_t smem_u32(const void* p) {
    uint32_t a;
    asm("{ .reg .u64 t; cvta.to.shared.u64 t, %1; cvt.u32.u64 %0, t; }" : "=r"(a) : "l"(p));
    return a;
}

__device__ __forceinline__ float tf32r(float x) {
    uint32_t u;
    asm("cvt.rna.tf32.f32 %0, %1;" : "=r"(u) : "f"(x));
    return __uint_as_float(u);
}

__device__ __forceinline__ uint32_t tf32u(uint32_t x) {
    uint32_t r;
    asm("cvt.rna.tf32.f32 %0, %1;" : "=r"(r) : "f"(__uint_as_float(x)));
    return r;
}

__device__ __forceinline__ void cp16(uint32_t dst, const void* src, int srcsize) {
    asm volatile("cp.async.cg.shared.global [%0], [%1], 16, %2;"
                 :: "r"(dst), "l"(src), "r"(srcsize) : "memory");
}

__device__ __forceinline__ void cp4(uint32_t dst, const void* src, int srcsize) {
    asm volatile("cp.async.ca.shared.global [%0], [%1], 4, %2;"
                 :: "r"(dst), "l"(src), "r"(srcsize) : "memory");
}

__device__ __forceinline__ void mma_tf32(float* c, const uint32_t* a, const uint32_t* b) {
    asm volatile(
        "mma.sync.aligned.m16n8k8.row.col.f32.tf32.tf32.f32 "
        "{%0,%1,%2,%3}, {%4,%5,%6,%7}, {%8,%9}, {%0,%1,%2,%3};"
        : "+f"(c[0]), "+f"(c[1]), "+f"(c[2]), "+f"(c[3])
        : "r"(a[0]), "r"(a[1]), "r"(a[2]), "r"(a[3]), "r"(b[0]), "r"(b[1]));
}

// ================= preprocessing =================
__global__ void round_w1_kernel(const float* __restrict__ W1) {
    int idx = blockIdx.x * blockDim.x + threadIdx.x;
    if (idx >= KPAD1 * FHID) return;
    int k = idx / FHID;
    g_w1r[idx] = (k < FIN) ? tf32r(W1[idx]) : 0.0f;
}

__global__ void round_w2_kernel(const float* __restrict__ W2) {
    int idx = blockIdx.x * blockDim.x + threadIdx.x;
    if (idx >= FHID * FOUT) return;
    g_w2r[idx] = tf32r(W2[idx]);
}

// ================= CSR build =================
__global__ void zero_cnt_kernel() {
    int i = blockIdx.x * blockDim.x + threadIdx.x;
    if (i < NN) g_cnt[i] = 0;
}

__global__ void count_deg_kernel(const int* __restrict__ dst) {
    int e = blockIdx.x * blockDim.x + threadIdx.x;
    if (e < NE) atomicAdd(&g_cnt[dst[e]], 1);
}

__global__ __launch_bounds__(1024)
void scan_block_kernel() {
    __shared__ int ws[32];
    int t = threadIdx.x, b = blockIdx.x;
    int i = b * 1024 + t;
    int v = (i < NN) ? g_cnt[i] : 0;
    if (i < NN) {
        float d = (float)v + 1.0f;
        g_dinv[i]   = rsqrtf(d);
        g_invdeg[i] = 1.0f / d;
    }
    int lane = t & 31, w = t >> 5;
    int x = v;
    #pragma unroll
    for (int o = 1; o < 32; o <<= 1) {
        int y = __shfl_up_sync(0xffffffffu, x, o);
        if (lane >= o) x += y;
    }
    if (lane == 31) ws[w] = x;
    __syncthreads();
    if (w == 0) {
        int s = ws[lane];
        #pragma unroll
        for (int o = 1; o < 32; o <<= 1) {
            int y = __shfl_up_sync(0xffffffffu, s, o);
            if (lane >= o) s += y;
        }
        ws[lane] = s;
    }
    __syncthreads();
    int pre = (w > 0) ? ws[w - 1] : 0;
    if (i < NN) g_offs[i] = pre + x - v;
    if (t == 1023) g_bsum[b] = pre + x;
}

__global__ void scan_bsum_kernel(int nblk) {
    __shared__ int s[64];
    int t = threadIdx.x;
    s[t] = (t < nblk) ? g_bsum[t] : 0;
    __syncthreads();
    if (t == 0) {
        int acc = 0;
        for (int i = 0; i < nblk; i++) { int v = s[i]; s[i] = acc; acc += v; }
    }
    __syncthreads();
    if (t < nblk) g_bsum[t] = s[t];
}

__global__ __launch_bounds__(1024)
void scan_add_kernel() {
    int t = threadIdx.x, b = blockIdx.x;
    int i = b * 1024 + t;
    if (i < NN) {
        int o = g_offs[i] + g_bsum[b];
        g_offs[i] = o;
        g_cur[i]  = o;
    }
    if (i == 0) g_offs[NN] = NE;
}

__global__ void fill_csr_kernel(const int* __restrict__ src, const int* __restrict__ dst) {
    int e = blockIdx.x * blockDim.x + threadIdx.x;
    if (e < NE) {
        int s = src[e];
        int d = dst[e];
        int p = atomicAdd(&g_cur[d], 1);
        g_csr_src[p]  = s;
        g_csr_coef[p] = g_dinv[s] * g_dinv[d];
    }
}

// ================= tf32 mma.sync GEMM =================
// C[M, NMAT] = A[M, KA] @ B[KAceil16, NMAT].  Block 128x128x16, 8 warps (4x2),
// warp tile 32x64, m16n8k8 tf32 mma, 3-stage cp.async pipeline.
// ALIGNED_A: A rows are 16B-aligned, KA % 16 == 0, data pre-rounded to tf32.
// Otherwise: A loaded with 4B cp.async (any alignment), OOB zero-filled,
// tf32 rounding applied in registers (ROUND_A).
template <int NMAT, int KA, int KTILES, bool ALIGNED_A, bool ROUND_A>
__global__ __launch_bounds__(256)
void mma_gemm_kernel(const float* __restrict__ A, const float* __restrict__ B,
                     float* __restrict__ C) {
    constexpr int S = 3;
    constexpr int AS_STRIDE = 20;
    constexpr int BS_STRIDE = 136;
    constexpr int A_FLOATS = 128 * AS_STRIDE;
    constexpr int B_FLOATS = 16 * BS_STRIDE;
    constexpr int STG = A_FLOATS + B_FLOATS;

    extern __shared__ float sm[];
    uint32_t smb = smem_u32(sm);

    int tid  = threadIdx.x;
    int lane = tid & 31;
    int w    = tid >> 5;
    int g    = lane >> 2;
    int tig  = lane & 3;
    int wm   = (w & 3) * 32;
    int wn   = (w >> 2) * 64;
    int m0   = blockIdx.y * 128;
    int n0   = blockIdx.x * 128;

    int a_row  = tid >> 1;
    int a_half = (tid & 1) * 8;
    int a_m    = m0 + a_row;
    bool a_ok  = (a_m < NN);
    const float* Ag = A + (size_t)(a_ok ? a_m : 0) * KA;
    uint32_t a_dst0 = smb + (uint32_t)(a_row * AS_STRIDE + a_half) * 4;

    int b_row = tid >> 4;
    int b_col = (tid & 15) * 8;
    const float* Bg = B + (size_t)b_row * NMAT + n0 + b_col;
    uint32_t b_dst0 = smb + (uint32_t)(A_FLOATS + b_row * BS_STRIDE + b_col) * 4;

    float c[2][8][4];
    #pragma unroll
    for (int mt = 0; mt < 2; mt++)
        #pragma unroll
        for (int nt = 0; nt < 8; nt++)
            #pragma unroll
            for (int q = 0; q < 4; q++) c[mt][nt][q] = 0.0f;

    // A-tile loader for one stage
    auto load_a = [&](int kt, uint32_t off) {
        if (ALIGNED_A) {
            const float* ga = Ag + kt * 16 + a_half;
            int sz = a_ok ? 16 : 0;
            cp16(a_dst0 + off,      ga,     sz);
            cp16(a_dst0 + off + 16, ga + 4, sz);
        } else {
            int c0 = kt * 16 + a_half;
            #pragma unroll
            for (int i = 0; i < 8; i++) {
                int col = c0 + i;
                int sz = (a_ok && col < KA) ? 4 : 0;
                int cc = (col < KA) ? col : (KA - 1);
                cp4(a_dst0 + off + i * 4, Ag + cc, sz);
            }
        }
    };

    #pragma unroll
    for (int s = 0; s < S - 1; s++) {
        uint32_t off = (uint32_t)(s * STG) * 4;
        load_a(s, off);
        const float* gb = Bg + (size_t)(s * 16) * NMAT;
        cp16(b_dst0 + off,      gb,     16);
        cp16(b_dst0 + off + 16, gb + 4, 16);
        asm volatile("cp.async.commit_group;" ::: "memory");
    }

    for (int kt = 0; kt < KTILES; kt++) {
        asm volatile("cp.async.wait_group %0;" :: "n"(S - 2) : "memory");
        __syncthreads();

        {
            int nk = kt + S - 1;
            if (nk < KTILES) {
                uint32_t off = (uint32_t)((nk % S) * STG) * 4;
                load_a(nk, off);
                const float* gb = Bg + (size_t)(nk * 16) * NMAT;
                cp16(b_dst0 + off,      gb,     16);
                cp16(b_dst0 + off + 16, gb + 4, 16);
            }
            asm volatile("cp.async.commit_group;" ::: "memory");
        }

        const float* As = sm + (kt % S) * STG;
        const float* Bs = As + A_FLOATS;

        #pragma unroll
        for (int kk = 0; kk < 16; kk += 8) {
            uint32_t a[2][4], b[8][2];
            #pragma unroll
            for (int mt = 0; mt < 2; mt++) {
                int r = wm + mt * 16 + g;
                a[mt][0] = __float_as_uint(As[r * AS_STRIDE + kk + tig]);
                a[mt][1] = __float_as_uint(As[(r + 8) * AS_STRIDE + kk + tig]);
                a[mt][2] = __float_as_uint(As[r * AS_STRIDE + kk + tig + 4]);
                a[mt][3] = __float_as_uint(As[(r + 8) * AS_STRIDE + kk + tig + 4]);
                if (ROUND_A) {
                    a[mt][0] = tf32u(a[mt][0]);
                    a[mt][1] = tf32u(a[mt][1]);
                    a[mt][2] = tf32u(a[mt][2]);
                    a[mt][3] = tf32u(a[mt][3]);
                }
            }
            #pragma unroll
            for (int nt = 0; nt < 8; nt++) {
                int ccol = wn + nt * 8 + g;
                b[nt][0] = __float_as_uint(Bs[(kk + tig) * BS_STRIDE + ccol]);
                b[nt][1] = __float_as_uint(Bs[(kk + tig + 4) * BS_STRIDE + ccol]);
            }
            #pragma unroll
            for (int mt = 0; mt < 2; mt++)
                #pragma unroll
                for (int nt = 0; nt < 8; nt++)
                    mma_tf32(c[mt][nt], a[mt], b[nt]);
        }
    }

    #pragma unroll
    for (int mt = 0; mt < 2; mt++) {
        int r0 = m0 + wm + mt * 16 + g;
        #pragma unroll
        for (int nt = 0; nt < 8; nt++) {
            int col = n0 + wn + nt * 8 + 2 * tig;
            if (r0 < NN)
                *(float2*)(C + (size_t)r0 * NMAT + col) = make_float2(c[mt][nt][0], c[mt][nt][1]);
            if (r0 + 8 < NN)
                *(float2*)(C + (size_t)(r0 + 8) * NMAT + col) = make_float2(c[mt][nt][2], c[mt][nt][3]);
        }
    }
}

// ================= fused aggregate + bias + BN + ELU (layer 1) =================
__device__ __forceinline__ float elu1(float x) { return x > 0.0f ? x : expm1f(x); }

__global__ __launch_bounds__(256)
void aggregate1_kernel(const float* __restrict__ bias,
                       const float* __restrict__ bnw, const float* __restrict__ bnb,
                       const float* __restrict__ bnm, const float* __restrict__ bnv) {
    const float* h = (const float*)g_h1;
    float* out = (float*)g_act1;
    constexpr int F = FHID;
    constexpr int V = F / 128;

    int warp = (blockIdx.x * blockDim.x + threadIdx.x) >> 5;
    int lane = threadIdx.x & 31;
    if (warp >= NN) return;
    int node = warp;

    float4 acc[V];
    {
        const float4* hn = (const float4*)(h + (size_t)node * F);
        float idg = g_invdeg[node];
        #pragma unroll
        for (int t = 0; t < V; t++) {
            float4 v = hn[lane + 32 * t];
            acc[t] = make_float4(v.x * idg, v.y * idg, v.z * idg, v.w * idg);
        }
    }

    int beg = g_offs[node];
    int end = g_offs[node + 1];
    for (int j = beg; j < end; j++) {
        int   s = g_csr_src[j];
        float cc = g_csr_coef[j];
        const float4* hs = (const float4*)(h + (size_t)s * F);
        #pragma unroll
        for (int t = 0; t < V; t++) {
            float4 v = hs[lane + 32 * t];
            acc[t].x += v.x * cc;
            acc[t].y += v.y * cc;
            acc[t].z += v.z * cc;
            acc[t].w += v.w * cc;
        }
    }

    #pragma unroll
    for (int t = 0; t < V; t++) {
        int f = (lane + 32 * t) * 4;
        float4 bb = *(const float4*)(bias + f);
        float4 w  = *(const float4*)(bnw + f);
        float4 b2 = *(const float4*)(bnb + f);
        float4 mn = *(const float4*)(bnm + f);
        float4 vr = *(const float4*)(bnv + f);
        float4 o;
        o.x = tf32r(elu1((acc[t].x + bb.x - mn.x) * rsqrtf(vr.x + BN_EPS) * w.x + b2.x));
        o.y = tf32r(elu1((acc[t].y + bb.y - mn.y) * rsqrtf(vr.y + BN_EPS) * w.y + b2.y));
        o.z = tf32r(elu1((acc[t].z + bb.z - mn.z) * rsqrtf(vr.z + BN_EPS) * w.z + b2.z));
        o.w = tf32r(elu1((acc[t].w + bb.w - mn.w) * rsqrtf(vr.w + BN_EPS) * w.w + b2.w));
        ((float4*)(out + (size_t)node * F))[lane + 32 * t] = o;
    }
}

// ===== layer 2 aggregate + BN + ELU, fused with softmax head =====
__global__ __launch_bounds__(256)
void aggregate2_head_kernel(const float* __restrict__ bias,
                            const float* __restrict__ bnw, const float* __restrict__ bnb,
                            const float* __restrict__ bnm, const float* __restrict__ bnv,
                            const float* __restrict__ Wp, const float* __restrict__ bp,
                            float* __restrict__ out_h, float* __restrict__ out_z) {
    constexpr int F = FOUT;
    __shared__ float sW[F * NCLS];
    __shared__ float sbp[NCLS];
    for (int i = threadIdx.x; i < F * NCLS; i += blockDim.x) sW[i] = Wp[i];
    if (threadIdx.x < NCLS) sbp[threadIdx.x] = bp[threadIdx.x];
    __syncthreads();

    const float* h = (const float*)g_h2;
    int warp = (blockIdx.x * blockDim.x + threadIdx.x) >> 5;
    int lane = threadIdx.x & 31;
    if (warp >= NN) return;
    int node = warp;

    float4 acc;
    {
        float4 v = ((const float4*)(h + (size_t)node * F))[lane];
        float idg = g_invdeg[node];
        acc = make_float4(v.x * idg, v.y * idg, v.z * idg, v.w * idg);
    }

    int beg = g_offs[node];
    int end = g_offs[node + 1];
    for (int j = beg; j < end; j++) {
        int   s = g_csr_src[j];
        float cc = g_csr_coef[j];
        float4 v = ((const float4*)(h + (size_t)s * F))[lane];
        acc.x += v.x * cc;
        acc.y += v.y * cc;
        acc.z += v.z * cc;
        acc.w += v.w * cc;
    }

    int f = lane * 4;
    float4 bb = *(const float4*)(bias + f);
    float4 w  = *(const float4*)(bnw + f);
    float4 b2 = *(const float4*)(bnb + f);
    float4 mn = *(const float4*)(bnm + f);
    float4 vr = *(const float4*)(bnv + f);
    float4 o;
    o.x = elu1((acc.x + bb.x - mn.x) * rsqrtf(vr.x + BN_EPS) * w.x + b2.x);
    o.y = elu1((acc.y + bb.y - mn.y) * rsqrtf(vr.y + BN_EPS) * w.y + b2.y);
    o.z = elu1((acc.z + bb.z - mn.z) * rsqrtf(vr.z + BN_EPS) * w.z + b2.z);
    o.w = elu1((acc.w + bb.w - mn.w) * rsqrtf(vr.w + BN_EPS) * w.w + b2.w);
    ((float4*)(out_h + (size_t)node * F))[lane] = o;

    // head: logits over lane-local 4 features, then warp reduce
    float p[NCLS];
    #pragma unroll
    for (int k = 0; k < NCLS; k++)
        p[k] = o.x * sW[(f + 0) * NCLS + k] + o.y * sW[(f + 1) * NCLS + k]
             + o.z * sW[(f + 2) * NCLS + k] + o.w * sW[(f + 3) * NCLS + k];
    #pragma unroll
    for (int off = 16; off > 0; off >>= 1)
        #pragma unroll
        for (int k = 0; k < NCLS; k++)
            p[k] += __shfl_xor_sync(0xffffffffu, p[k], off);

    #pragma unroll
    for (int k = 0; k < NCLS; k++) p[k] += sbp[k];
    float m = p[0];
    #pragma unroll
    for (int k = 1; k < NCLS; k++) m = fmaxf(m, p[k]);
    float ssum = 0.0f;
    #pragma unroll
    for (int k = 0; k < NCLS; k++) { p[k] = expf(p[k] - m); ssum += p[k]; }
    float inv = 1.0f / ssum;
    if (lane < NCLS) out_z[(size_t)node * NCLS + lane] = p[lane] * inv;
}

// ================= host =================
extern "C" void kernel_launch(void* const* d_in, const int* in_sizes, int n_in,
                              void* d_out, int out_size) {
    const float* x    = (const float*)d_in[0];
    const int*   ei   = (const int*)d_in[1];
    const float* W1   = (const float*)d_in[2];
    const float* b1   = (const float*)d_in[3];
    const float* bn1w = (const float*)d_in[4];
    const float* bn1b = (const float*)d_in[5];
    const float* bn1m = (const float*)d_in[6];
    const float* bn1v = (const float*)d_in[7];
    const float* W2   = (const float*)d_in[8];
    const float* b2   = (const float*)d_in[9];
    const float* bn2w = (const float*)d_in[10];
    const float* bn2b = (const float*)d_in[11];
    const float* bn2m = (const float*)d_in[12];
    const float* bn2v = (const float*)d_in[13];
    const float* Wp   = (const float*)d_in[14];
    const float* bp   = (const float*)d_in[15];

    const int* src = ei;
    const int* dst = ei + NE;

    float* out_h = (float*)d_out;
    float* out_z = out_h + (size_t)NN * FOUT;

    void *p_w1r, *p_w2r, *p_act1, *p_h1, *p_h2;
    cudaGetSymbolAddress(&p_w1r,  g_w1r);
    cudaGetSymbolAddress(&p_w2r,  g_w2r);
    cudaGetSymbolAddress(&p_act1, g_act1);
    cudaGetSymbolAddress(&p_h1,   g_h1);
    cudaGetSymbolAddress(&p_h2,   g_h2);

    constexpr int STG_BYTES = (128 * 20 + 16 * 136) * 4;
    constexpr int SMEM_GEMM = 3 * STG_BYTES;
    constexpr int KT1 = (FIN + 15) / 16;   // 90
    static bool attr_set = false;
    if (!attr_set) {
        cudaFuncSetAttribute(mma_gemm_kernel<FHID, FIN, KT1, false, true>,
                             cudaFuncAttributeMaxDynamicSharedMemorySize, SMEM_GEMM);
        cudaFuncSetAttribute(mma_gemm_kernel<FOUT, FHID, FHID / 16, true, false>,
                             cudaFuncAttributeMaxDynamicSharedMemorySize, SMEM_GEMM);
        attr_set = true;
    }

    const int NODE_BLKS = (NN + 255) / 256;
    const int EDGE_BLKS = (NE + 255) / 256;
    const int SCAN_BLKS = (NN + 1023) / 1024;
    const int MTILES    = (NN + 127) / 128;

    // weight rounding (tiny)
    round_w1_kernel<<<(KPAD1 * FHID + 255) / 256, 256>>>(W1);
    round_w2_kernel<<<(FHID * FOUT + 255) / 256, 256>>>(W2);

    // CSR build
    zero_cnt_kernel<<<NODE_BLKS, 256>>>();
    count_deg_kernel<<<EDGE_BLKS, 256>>>(dst);
    scan_block_kernel<<<SCAN_BLKS, 1024>>>();
    scan_bsum_kernel<<<1, 64>>>(SCAN_BLKS);
    scan_add_kernel<<<SCAN_BLKS, 1024>>>();
    fill_csr_kernel<<<EDGE_BLKS, 256>>>(src, dst);

    // layer 1 (A loaded directly from x, rounded in-register)
    mma_gemm_kernel<FHID, FIN, KT1, false, true>
        <<<dim3(2, MTILES), 256, SMEM_GEMM>>>(x, (const float*)p_w1r, (float*)p_h1);
    aggregate1_kernel<<<(NN * 32) / 256, 256>>>(b1, bn1w, bn1b, bn1m, bn1v);

    // layer 2
    mma_gemm_kernel<FOUT, FHID, FHID / 16, true, false>
        <<<dim3(1, MTILES), 256, SMEM_GEMM>>>((const float*)p_act1, (const float*)p_w2r, (float*)p_h2);
    aggregate2_head_kernel<<<(NN * 32) / 256, 256>>>(b2, bn2w, bn2b, bn2m, bn2v,
                                                     Wp, bp, out_h, out_z);
}

// round 5
// speedup vs baseline: 2.6689x; 1.1833x over previous
#include <cuda_runtime.h>
#include <math.h>
#include <stdint.h>

#define NN   50000
#define NE   800000
#define FIN  1433
#define KPAD1 1440
#define FHID 256
#define FOUT 128
#define NCLS 7
#define BN_EPS 1e-5f

// ---------------- scratch (device globals; no runtime allocation) ----------------
__device__ int   g_cnt[NN];
__device__ int   g_offs[NN + 1];
__device__ int   g_cur[NN];
__device__ int   g_bsum[64];
__device__ int   g_csr_src[NE];
__device__ float g_csr_coef[NE];
__device__ float g_dinv[NN];
__device__ float g_invdeg[NN];
__device__ float g_w1r[(size_t)KPAD1 * FHID];   // W1 [K,N] tf32-rounded, K zero-padded
__device__ float g_w2r[(size_t)FHID * FOUT];    // W2 [K,N] tf32-rounded
__device__ float g_h1[(size_t)NN * FHID];       // x @ W1
__device__ float g_act1[(size_t)NN * FHID];     // ELU(BN(agg1)), tf32-rounded
__device__ float g_h2[(size_t)NN * FOUT];       // act1 @ W2

// ================= helpers =================
__device__ __forceinline__ uint32_t smem_u32(const void* p) {
    uint32_t a;
    asm("{ .reg .u64 t; cvta.to.shared.u64 t, %1; cvt.u32.u64 %0, t; }" : "=r"(a) : "l"(p));
    return a;
}

__device__ __forceinline__ float tf32r(float x) {
    uint32_t u;
    asm("cvt.rna.tf32.f32 %0, %1;" : "=r"(u) : "f"(x));
    return __uint_as_float(u);
}

__device__ __forceinline__ uint32_t tf32u(uint32_t x) {
    uint32_t r;
    asm("cvt.rna.tf32.f32 %0, %1;" : "=r"(r) : "f"(__uint_as_float(x)));
    return r;
}

__device__ __forceinline__ void cp16(uint32_t dst, const void* src, int srcsize) {
    asm volatile("cp.async.cg.shared.global [%0], [%1], 16, %2;"
                 :: "r"(dst), "l"(src), "r"(srcsize) : "memory");
}

__device__ __forceinline__ void cp4(uint32_t dst, const void* src, int srcsize) {
    asm volatile("cp.async.ca.shared.global [%0], [%1], 4, %2;"
                 :: "r"(dst), "l"(src), "r"(srcsize) : "memory");
}

__device__ __forceinline__ void mma_tf32(float* c, const uint32_t* a, const uint32_t* b) {
    asm volatile(
        "mma.sync.aligned.m16n8k8.row.col.f32.tf32.tf32.f32 "
        "{%0,%1,%2,%3}, {%4,%5,%6,%7}, {%8,%9}, {%0,%1,%2,%3};"
        : "+f"(c[0]), "+f"(c[1]), "+f"(c[2]), "+f"(c[3])
        : "r"(a[0]), "r"(a[1]), "r"(a[2]), "r"(a[3]), "r"(b[0]), "r"(b[1]));
}

// ================= preprocessing =================
__global__ void round_w1_kernel(const float* __restrict__ W1) {
    int idx = blockIdx.x * blockDim.x + threadIdx.x;
    if (idx >= KPAD1 * FHID) return;
    int k = idx / FHID;
    g_w1r[idx] = (k < FIN) ? tf32r(W1[idx]) : 0.0f;
}

__global__ void round_w2_kernel(const float* __restrict__ W2) {
    int idx = blockIdx.x * blockDim.x + threadIdx.x;
    if (idx >= FHID * FOUT) return;
    g_w2r[idx] = tf32r(W2[idx]);
}

// ================= CSR build =================
__global__ void zero_cnt_kernel() {
    int i = blockIdx.x * blockDim.x + threadIdx.x;
    if (i < NN) g_cnt[i] = 0;
}

__global__ void count_deg_kernel(const int* __restrict__ dst) {
    int e = blockIdx.x * blockDim.x + threadIdx.x;
    if (e < NE) atomicAdd(&g_cnt[dst[e]], 1);
}

__global__ __launch_bounds__(1024)
void scan_block_kernel() {
    __shared__ int ws[32];
    int t = threadIdx.x, b = blockIdx.x;
    int i = b * 1024 + t;
    int v = (i < NN) ? g_cnt[i] : 0;
    if (i < NN) {
        float d = (float)v + 1.0f;
        g_dinv[i]   = rsqrtf(d);
        g_invdeg[i] = 1.0f / d;
    }
    int lane = t & 31, w = t >> 5;
    int x = v;
    #pragma unroll
    for (int o = 1; o < 32; o <<= 1) {
        int y = __shfl_up_sync(0xffffffffu, x, o);
        if (lane >= o) x += y;
    }
    if (lane == 31) ws[w] = x;
    __syncthreads();
    if (w == 0) {
        int s = ws[lane];
        #pragma unroll
        for (int o = 1; o < 32; o <<= 1) {
            int y = __shfl_up_sync(0xffffffffu, s, o);
            if (lane >= o) s += y;
        }
        ws[lane] = s;
    }
    __syncthreads();
    int pre = (w > 0) ? ws[w - 1] : 0;
    if (i < NN) g_offs[i] = pre + x - v;
    if (t == 1023) g_bsum[b] = pre + x;
}

__global__ void scan_bsum_kernel(int nblk) {
    __shared__ int s[64];
    int t = threadIdx.x;
    s[t] = (t < nblk) ? g_bsum[t] : 0;
    __syncthreads();
    if (t == 0) {
        int acc = 0;
        for (int i = 0; i < nblk; i++) { int v = s[i]; s[i] = acc; acc += v; }
    }
    __syncthreads();
    if (t < nblk) g_bsum[t] = s[t];
}

__global__ __launch_bounds__(1024)
void scan_add_kernel() {
    int t = threadIdx.x, b = blockIdx.x;
    int i = b * 1024 + t;
    if (i < NN) {
        int o = g_offs[i] + g_bsum[b];
        g_offs[i] = o;
        g_cur[i]  = o;
    }
    if (i == 0) g_offs[NN] = NE;
}

__global__ void fill_csr_kernel(const int* __restrict__ src, const int* __restrict__ dst) {
    int e = blockIdx.x * blockDim.x + threadIdx.x;
    if (e < NE) {
        int s = src[e];
        int d = dst[e];
        int p = atomicAdd(&g_cur[d], 1);
        g_csr_src[p]  = s;
        g_csr_coef[p] = g_dinv[s] * g_dinv[d];
    }
}

// ================= tf32 mma.sync GEMM =================
// C[M, NMAT] = A[M, KA] @ B[KAceil16, NMAT].
// Block 128 x (WNW*64), WNW*4 warps (4 in M x WNW in N), warp tile 32x64,
// m16n8k8 tf32 mma, 3-stage cp.async pipeline.
// ALIGNED_A: A rows 16B-aligned, KA%16==0, pre-rounded tf32.
// Else: 4B cp.async loads (any alignment), OOB zero-fill, tf32 round in regs.
template <int NMAT, int KA, int KTILES, bool ALIGNED_A, bool ROUND_A, int WNW>
__global__ __launch_bounds__(WNW * 128)
void mma_gemm_kernel(const float* __restrict__ A, const float* __restrict__ B,
                     float* __restrict__ C) {
    constexpr int S = 3;
    constexpr int THREADS = WNW * 128;
    constexpr int BLOCKN = WNW * 64;
    constexpr int AS_STRIDE = 20;
    constexpr int BS_STRIDE = BLOCKN + 8;         // 136 / 264 — both ≡ 8 (mod 32): bank-safe
    constexpr int A_FLOATS = 128 * AS_STRIDE;
    constexpr int B_FLOATS = 16 * BS_STRIDE;
    constexpr int STG = A_FLOATS + B_FLOATS;
    constexpr int FA = 2048 / THREADS;            // A floats per thread per stage (8 or 4)

    extern __shared__ float sm[];
    uint32_t smb = smem_u32(sm);

    int tid  = threadIdx.x;
    int lane = tid & 31;
    int w    = tid >> 5;
    int g    = lane >> 2;
    int tig  = lane & 3;
    int wm   = (w & 3) * 32;
    int wn   = (w >> 2) * 64;
    int m0   = blockIdx.y * 128;
    int n0   = blockIdx.x * BLOCKN;

    int a_row  = tid / (16 / FA);
    int a_off  = (tid % (16 / FA)) * FA;
    int a_m    = m0 + a_row;
    bool a_ok  = (a_m < NN);
    const float* Ag = A + (size_t)(a_ok ? a_m : 0) * KA;
    uint32_t a_dst0 = smb + (uint32_t)(a_row * AS_STRIDE + a_off) * 4;

    int b_row = tid / (BLOCKN / 8);
    int b_col = (tid % (BLOCKN / 8)) * 8;
    const float* Bg = B + (size_t)b_row * NMAT + n0 + b_col;
    uint32_t b_dst0 = smb + (uint32_t)(A_FLOATS + b_row * BS_STRIDE + b_col) * 4;

    float c[2][8][4];
    #pragma unroll
    for (int mt = 0; mt < 2; mt++)
        #pragma unroll
        for (int nt = 0; nt < 8; nt++)
            #pragma unroll
            for (int q = 0; q < 4; q++) c[mt][nt][q] = 0.0f;

    auto load_a = [&](int kt, uint32_t off) {
        if (ALIGNED_A) {
            const float* ga = Ag + kt * 16 + a_off;
            int sz = a_ok ? 16 : 0;
            cp16(a_dst0 + off, ga, sz);
            if (FA == 8) cp16(a_dst0 + off + 16, ga + 4, sz);
        } else {
            int c0 = kt * 16 + a_off;
            #pragma unroll
            for (int i = 0; i < FA; i++) {
                int col = c0 + i;
                int sz = (a_ok && col < KA) ? 4 : 0;
                int cc = (col < KA) ? col : (KA - 1);
                cp4(a_dst0 + off + i * 4, Ag + cc, sz);
            }
        }
    };

    #pragma unroll
    for (int s = 0; s < S - 1; s++) {
        uint32_t off = (uint32_t)(s * STG) * 4;
        load_a(s, off);
        const float* gb = Bg + (size_t)(s * 16) * NMAT;
        cp16(b_dst0 + off,      gb,     16);
        cp16(b_dst0 + off + 16, gb + 4, 16);
        asm volatile("cp.async.commit_group;" ::: "memory");
    }

    for (int kt = 0; kt < KTILES; kt++) {
        asm volatile("cp.async.wait_group %0;" :: "n"(S - 2) : "memory");
        __syncthreads();

        {
            int nk = kt + S - 1;
            if (nk < KTILES) {
                uint32_t off = (uint32_t)((nk % S) * STG) * 4;
                load_a(nk, off);
                const float* gb = Bg + (size_t)(nk * 16) * NMAT;
                cp16(b_dst0 + off,      gb,     16);
                cp16(b_dst0 + off + 16, gb + 4, 16);
            }
            asm volatile("cp.async.commit_group;" ::: "memory");
        }

        const float* As = sm + (kt % S) * STG;
        const float* Bs = As + A_FLOATS;

        #pragma unroll
        for (int kk = 0; kk < 16; kk += 8) {
            uint32_t a[2][4], b[8][2];
            #pragma unroll
            for (int mt = 0; mt < 2; mt++) {
                int r = wm + mt * 16 + g;
                a[mt][0] = __float_as_uint(As[r * AS_STRIDE + kk + tig]);
                a[mt][1] = __float_as_uint(As[(r + 8) * AS_STRIDE + kk + tig]);
                a[mt][2] = __float_as_uint(As[r * AS_STRIDE + kk + tig + 4]);
                a[mt][3] = __float_as_uint(As[(r + 8) * AS_STRIDE + kk + tig + 4]);
                if (ROUND_A) {
                    a[mt][0] = tf32u(a[mt][0]);
                    a[mt][1] = tf32u(a[mt][1]);
                    a[mt][2] = tf32u(a[mt][2]);
                    a[mt][3] = tf32u(a[mt][3]);
                }
            }
            #pragma unroll
            for (int nt = 0; nt < 8; nt++) {
                int ccol = wn + nt * 8 + g;
                b[nt][0] = __float_as_uint(Bs[(kk + tig) * BS_STRIDE + ccol]);
                b[nt][1] = __float_as_uint(Bs[(kk + tig + 4) * BS_STRIDE + ccol]);
            }
            #pragma unroll
            for (int mt = 0; mt < 2; mt++)
                #pragma unroll
                for (int nt = 0; nt < 8; nt++)
                    mma_tf32(c[mt][nt], a[mt], b[nt]);
        }
    }

    #pragma unroll
    for (int mt = 0; mt < 2; mt++) {
        int r0 = m0 + wm + mt * 16 + g;
        #pragma unroll
        for (int nt = 0; nt < 8; nt++) {
            int col = n0 + wn + nt * 8 + 2 * tig;
            if (r0 < NN)
                *(float2*)(C + (size_t)r0 * NMAT + col) = make_float2(c[mt][nt][0], c[mt][nt][1]);
            if (r0 + 8 < NN)
                *(float2*)(C + (size_t)(r0 + 8) * NMAT + col) = make_float2(c[mt][nt][2], c[mt][nt][3]);
        }
    }
}

// ================= fused aggregate + bias + BN + ELU (layer 1) =================
__device__ __forceinline__ float elu1(float x) { return x > 0.0f ? x : expm1f(x); }

__global__ __launch_bounds__(256)
void aggregate1_kernel(const float* __restrict__ bias,
                       const float* __restrict__ bnw, const float* __restrict__ bnb,
                       const float* __restrict__ bnm, const float* __restrict__ bnv) {
    const float* h = (const float*)g_h1;
    float* out = (float*)g_act1;
    constexpr int F = FHID;
    constexpr int V = F / 128;

    int warp = (blockIdx.x * blockDim.x + threadIdx.x) >> 5;
    int lane = threadIdx.x & 31;
    if (warp >= NN) return;
    int node = warp;

    float4 acc[V];
    {
        const float4* hn = (const float4*)(h + (size_t)node * F);
        float idg = g_invdeg[node];
        #pragma unroll
        for (int t = 0; t < V; t++) {
            float4 v = hn[lane + 32 * t];
            acc[t] = make_float4(v.x * idg, v.y * idg, v.z * idg, v.w * idg);
        }
    }

    int beg = g_offs[node];
    int end = g_offs[node + 1];
    for (int j = beg; j < end; j++) {
        int   s = g_csr_src[j];
        float cc = g_csr_coef[j];
        const float4* hs = (const float4*)(h + (size_t)s * F);
        #pragma unroll
        for (int t = 0; t < V; t++) {
            float4 v = hs[lane + 32 * t];
            acc[t].x += v.x * cc;
            acc[t].y += v.y * cc;
            acc[t].z += v.z * cc;
            acc[t].w += v.w * cc;
        }
    }

    #pragma unroll
    for (int t = 0; t < V; t++) {
        int f = (lane + 32 * t) * 4;
        float4 bb = *(const float4*)(bias + f);
        float4 w  = *(const float4*)(bnw + f);
        float4 b2 = *(const float4*)(bnb + f);
        float4 mn = *(const float4*)(bnm + f);
        float4 vr = *(const float4*)(bnv + f);
        float4 o;
        o.x = tf32r(elu1((acc[t].x + bb.x - mn.x) * rsqrtf(vr.x + BN_EPS) * w.x + b2.x));
        o.y = tf32r(elu1((acc[t].y + bb.y - mn.y) * rsqrtf(vr.y + BN_EPS) * w.y + b2.y));
        o.z = tf32r(elu1((acc[t].z + bb.z - mn.z) * rsqrtf(vr.z + BN_EPS) * w.z + b2.z));
        o.w = tf32r(elu1((acc[t].w + bb.w - mn.w) * rsqrtf(vr.w + BN_EPS) * w.w + b2.w));
        ((float4*)(out + (size_t)node * F))[lane + 32 * t] = o;
    }
}

// ===== layer 2 aggregate + BN + ELU, fused with softmax head =====
__global__ __launch_bounds__(256)
void aggregate2_head_kernel(const float* __restrict__ bias,
                            const float* __restrict__ bnw, const float* __restrict__ bnb,
                            const float* __restrict__ bnm, const float* __restrict__ bnv,
                            const float* __restrict__ Wp, const float* __restrict__ bp,
                            float* __restrict__ out_h, float* __restrict__ out_z) {
    constexpr int F = FOUT;
    __shared__ float sW[F * NCLS];
    __shared__ float sbp[NCLS];
    for (int i = threadIdx.x; i < F * NCLS; i += blockDim.x) sW[i] = Wp[i];
    if (threadIdx.x < NCLS) sbp[threadIdx.x] = bp[threadIdx.x];
    __syncthreads();

    const float* h = (const float*)g_h2;
    int warp = (blockIdx.x * blockDim.x + threadIdx.x) >> 5;
    int lane = threadIdx.x & 31;
    if (warp >= NN) return;
    int node = warp;

    float4 acc;
    {
        float4 v = ((const float4*)(h + (size_t)node * F))[lane];
        float idg = g_invdeg[node];
        acc = make_float4(v.x * idg, v.y * idg, v.z * idg, v.w * idg);
    }

    int beg = g_offs[node];
    int end = g_offs[node + 1];
    for (int j = beg; j < end; j++) {
        int   s = g_csr_src[j];
        float cc = g_csr_coef[j];
        float4 v = ((const float4*)(h + (size_t)s * F))[lane];
        acc.x += v.x * cc;
        acc.y += v.y * cc;
        acc.z += v.z * cc;
        acc.w += v.w * cc;
    }

    int f = lane * 4;
    float4 bb = *(const float4*)(bias + f);
    float4 w  = *(const float4*)(bnw + f);
    float4 b2 = *(const float4*)(bnb + f);
    float4 mn = *(const float4*)(bnm + f);
    float4 vr = *(const float4*)(bnv + f);
    float4 o;
    o.x = elu1((acc.x + bb.x - mn.x) * rsqrtf(vr.x + BN_EPS) * w.x + b2.x);
    o.y = elu1((acc.y + bb.y - mn.y) * rsqrtf(vr.y + BN_EPS) * w.y + b2.y);
    o.z = elu1((acc.z + bb.z - mn.z) * rsqrtf(vr.z + BN_EPS) * w.z + b2.z);
    o.w = elu1((acc.w + bb.w - mn.w) * rsqrtf(vr.w + BN_EPS) * w.w + b2.w);
    ((float4*)(out_h + (size_t)node * F))[lane] = o;

    float p[NCLS];
    #pragma unroll
    for (int k = 0; k < NCLS; k++)
        p[k] = o.x * sW[(f + 0) * NCLS + k] + o.y * sW[(f + 1) * NCLS + k]
             + o.z * sW[(f + 2) * NCLS + k] + o.w * sW[(f + 3) * NCLS + k];
    #pragma unroll
    for (int off = 16; off > 0; off >>= 1)
        #pragma unroll
        for (int k = 0; k < NCLS; k++)
            p[k] += __shfl_xor_sync(0xffffffffu, p[k], off);

    #pragma unroll
    for (int k = 0; k < NCLS; k++) p[k] += sbp[k];
    float m = p[0];
    #pragma unroll
    for (int k = 1; k < NCLS; k++) m = fmaxf(m, p[k]);
    float ssum = 0.0f;
    #pragma unroll
    for (int k = 0; k < NCLS; k++) { p[k] = expf(p[k] - m); ssum += p[k]; }
    float inv = 1.0f / ssum;
    if (lane < NCLS) out_z[(size_t)node * NCLS + lane] = p[lane] * inv;
}

// ================= host =================
extern "C" void kernel_launch(void* const* d_in, const int* in_sizes, int n_in,
                              void* d_out, int out_size) {
    const float* x    = (const float*)d_in[0];
    const int*   ei   = (const int*)d_in[1];
    const float* W1   = (const float*)d_in[2];
    const float* b1   = (const float*)d_in[3];
    const float* bn1w = (const float*)d_in[4];
    const float* bn1b = (const float*)d_in[5];
    const float* bn1m = (const float*)d_in[6];
    const float* bn1v = (const float*)d_in[7];
    const float* W2   = (const float*)d_in[8];
    const float* b2   = (const float*)d_in[9];
    const float* bn2w = (const float*)d_in[10];
    const float* bn2b = (const float*)d_in[11];
    const float* bn2m = (const float*)d_in[12];
    const float* bn2v = (const float*)d_in[13];
    const float* Wp   = (const float*)d_in[14];
    const float* bp   = (const float*)d_in[15];

    const int* src = ei;
    const int* dst = ei + NE;

    float* out_h = (float*)d_out;
    float* out_z = out_h + (size_t)NN * FOUT;

    void *p_w1r, *p_w2r, *p_act1, *p_h1, *p_h2;
    cudaGetSymbolAddress(&p_w1r,  g_w1r);
    cudaGetSymbolAddress(&p_w2r,  g_w2r);
    cudaGetSymbolAddress(&p_act1, g_act1);
    cudaGetSymbolAddress(&p_h1,   g_h1);
    cudaGetSymbolAddress(&p_h2,   g_h2);

    constexpr int KT1 = (FIN + 15) / 16;                         // 90
    constexpr int SMEM_G1 = 3 * (128 * 20 + 16 * 264) * 4;       // 81408
    constexpr int SMEM_G2 = 3 * (128 * 20 + 16 * 136) * 4;       // 56832

    static cudaStream_t s_side = nullptr;
    static cudaEvent_t ev_fork = nullptr, ev_join = nullptr;
    if (!s_side) {
        cudaStreamCreateWithFlags(&s_side, cudaStreamNonBlocking);
        cudaEventCreateWithFlags(&ev_fork, cudaEventDisableTiming);
        cudaEventCreateWithFlags(&ev_join, cudaEventDisableTiming);
        cudaFuncSetAttribute(mma_gemm_kernel<FHID, FIN, KT1, false, true, 4>,
                             cudaFuncAttributeMaxDynamicSharedMemorySize, SMEM_G1);
        cudaFuncSetAttribute(mma_gemm_kernel<FOUT, FHID, FHID / 16, true, false, 2>,
                             cudaFuncAttributeMaxDynamicSharedMemorySize, SMEM_G2);
    }

    const int NODE_BLKS = (NN + 255) / 256;
    const int EDGE_BLKS = (NE + 255) / 256;
    const int SCAN_BLKS = (NN + 1023) / 1024;
    const int MTILES    = (NN + 127) / 128;

    // ---- fork: CSR build on side stream, concurrent with GEMM1 ----
    cudaEventRecord(ev_fork, 0);
    cudaStreamWaitEvent(s_side, ev_fork, 0);

    zero_cnt_kernel<<<NODE_BLKS, 256, 0, s_side>>>();
    count_deg_kernel<<<EDGE_BLKS, 256, 0, s_side>>>(dst);
    scan_block_kernel<<<SCAN_BLKS, 1024, 0, s_side>>>();
    scan_bsum_kernel<<<1, 64, 0, s_side>>>(SCAN_BLKS);
    scan_add_kernel<<<SCAN_BLKS, 1024, 0, s_side>>>();
    fill_csr_kernel<<<EDGE_BLKS, 256, 0, s_side>>>(src, dst);
    cudaEventRecord(ev_join, s_side);

    // ---- main stream: weights + GEMM1 ----
    round_w1_kernel<<<(KPAD1 * FHID + 255) / 256, 256>>>(W1);
    round_w2_kernel<<<(FHID * FOUT + 255) / 256, 256>>>(W2);

    mma_gemm_kernel<FHID, FIN, KT1, false, true, 4>
        <<<dim3(1, MTILES), 512, SMEM_G1>>>(x, (const float*)p_w1r, (float*)p_h1);

    // ---- join: aggregation needs CSR ----
    cudaStreamWaitEvent(0, ev_join, 0);

    aggregate1_kernel<<<(NN * 32) / 256, 256>>>(b1, bn1w, bn1b, bn1m, bn1v);

    mma_gemm_kernel<FOUT, FHID, FHID / 16, true, false, 2>
        <<<dim3(1, MTILES), 256, SMEM_G2>>>((const float*)p_act1, (const float*)p_w2r, (float*)p_h2);

    aggregate2_head_kernel<<<(NN * 32) / 256, 256>>>(b2, bn2w, bn2b, bn2m, bn2v,
                                                     Wp, bp, out_h, out_z);
}